// round 16
// baseline (speedup 1.0000x reference)
#include <cuda_runtime.h>

typedef unsigned long long ull;

#define TLEN 4000
#define HID  64
#define BT   2
#define NTHR 256

__device__ __forceinline__ void ffma2(ull &d, ull a, ull b) {
    asm("fma.rn.f32x2 %0, %1, %2, %0;" : "+l"(d) : "l"(a), "l"(b));
}
__device__ __forceinline__ ull mulx2(ull a, ull b) {
    ull r;
    asm("mul.rn.f32x2 %0, %1, %2;" : "=l"(r) : "l"(a), "l"(b));
    return r;
}
__device__ __forceinline__ float2 unpack2(ull v) {
    float2 r;
    asm("mov.b64 {%0, %1}, %2;" : "=f"(r.x), "=f"(r.y) : "l"(v));
    return r;
}
__device__ __forceinline__ ull pack2(float x, float y) {
    ull r;
    asm("mov.b64 %0, {%1, %2};" : "=l"(r) : "f"(x), "f"(y));
    return r;
}
__device__ __forceinline__ float hsum2(ull a, ull b) {
    ull s;
    asm("add.rn.f32x2 %0, %1, %2;" : "=l"(s) : "l"(a), "l"(b));
    float2 f = unpack2(s);
    return f.x + f.y;
}
__device__ __forceinline__ float tanha(float x) {
    float r;
    asm("tanh.approx.f32 %0, %1;" : "=f"(r) : "f"(x));
    return r;
}
// Sigmoid from a PRE-HALVED argument: sigmoid(2*xh) = 0.5*tanh(xh) + 0.5
__device__ __forceinline__ float fsigmoid_pre(float xh) {
    return fmaf(tanha(xh), 0.5f, 0.5f);
}

__global__ void __launch_bounds__(NTHR, 1)
lstm2_r16(const float* __restrict__ x,
          const float* __restrict__ W_ih0,
          const float* __restrict__ W_hh0,
          const float* __restrict__ b_ih0,
          const float* __restrict__ b_hh0,
          const float* __restrict__ W_ih1,
          const float* __restrict__ W_hh1,
          const float* __restrict__ b_ih1,
          const float* __restrict__ b_hh1,
          const float* __restrict__ W_fc,
          const float* __restrict__ b_fc,
          float* __restrict__ out)
{
    __shared__ __align__(16) float sh_x[BT * TLEN];       // 32 KB staged input
    __shared__ __align__(16) float sh_h[2][BT][2 * HID];  // dbl-buffered [h0|h1]
    __shared__ __align__(16) float sh_s[8][32][4];        // warp-local gate xchg

    const int tid   = threadIdx.x;
    const int w     = tid >> 5;
    const int l     = tid & 31;
    const int j     = l & 7;          // unit-local
    const int q     = l >> 3;         // gate index (i,f,g,o) AND pointwise combo
    const int u     = 8 * w + j;      // unit 0..63
    const int row   = q * HID + u;    // gate row this thread owns
    const int bbase = blockIdx.x * BT;

    // Stage x (two contiguous batch rows)
    {
        const float4* xg = (const float4*)(x + (size_t)bbase * TLEN);
        float4* xs = (float4*)sh_x;
        for (int i = tid; i < BT * TLEN / 4; i += NTHR) xs[i] = xg[i];
    }
    ((float2*)sh_h)[tid] = make_float2(0.0f, 0.0f);   // zero both slots (512 f)

    // Per-thread weight rows in registers (packed f32 pairs).
    // Sigmoid-gate rows (q != 2) are PRE-HALVED so the pointwise sigmoid
    // needs no 0.5*x multiply (exact scaling: exponent decrement).
    ull wA[32], wI[32], wH[32];   // W_hh0 / W_ih1 / W_hh1 row `row`
    {
        const ulonglong2* p = (const ulonglong2*)(W_hh0 + row * HID);
        #pragma unroll
        for (int t = 0; t < 16; t++) { ulonglong2 v = p[t]; wA[2*t] = v.x; wA[2*t+1] = v.y; }
        p = (const ulonglong2*)(W_ih1 + row * HID);
        #pragma unroll
        for (int t = 0; t < 16; t++) { ulonglong2 v = p[t]; wI[2*t] = v.x; wI[2*t+1] = v.y; }
        p = (const ulonglong2*)(W_hh1 + row * HID);
        #pragma unroll
        for (int t = 0; t < 16; t++) { ulonglong2 v = p[t]; wH[2*t] = v.x; wH[2*t+1] = v.y; }
    }
    const float gsc = (q == 2) ? 1.0f : 0.5f;     // tanh row unscaled
    if (q != 2) {
        const ull half2 = pack2(0.5f, 0.5f);
        #pragma unroll
        for (int t = 0; t < 32; t++) wA[t] = mulx2(wA[t], half2);
        #pragma unroll
        for (int t = 0; t < 32; t++) wI[t] = mulx2(wI[t], half2);
        #pragma unroll
        for (int t = 0; t < 32; t++) wH[t] = mulx2(wH[t], half2);
    }
    const float wx    = W_ih0[row] * gsc;
    const float biasA = (b_ih0[row] + b_hh0[row]) * gsc;
    const float biasB = (b_ih1[row] + b_hh1[row]) * gsc;

    // Pointwise combo for this lane: q -> (layer Lq, batch bq), unit u.
    const int Lq = q >> 1;
    const int bq = q & 1;
    const int hoff = Lq * HID + u;
    // Activity window: q<2 -> k in [0,TLEN); q>=2 -> k in [1,TLEN+1).
    const int klo = (q >= 2) ? 1 : 0;
    float c = 0.0f;

    __syncthreads();

    // Iter k: matvec gA(k) [layer0 step k] + gB(k-1) [layer1 step k-1],
    // warp-local pointwise -> h0(k), h1(k-1). ONE CTA barrier per step.
    for (int k = 0; k <= TLEN; ++k) {
        const int rs = (k + 1) & 1;   // read slot  (= writes of iter k-1)
        const int ws = k & 1;         // write slot
        // ---- fused matvec ----
        {
            const int xk = (k < TLEN) ? k : TLEN - 1;
            const float xa = sh_x[xk];
            const float xb = sh_x[TLEN + xk];
            ull aA0x = pack2(fmaf(xa, wx, biasA), 0.0f), aA0y = pack2(0.0f, 0.0f);
            ull aA1x = pack2(fmaf(xb, wx, biasA), 0.0f), aA1y = pack2(0.0f, 0.0f);
            ull aB0x = pack2(biasB, 0.0f),               aB0y = pack2(0.0f, 0.0f);
            ull aB1x = aB0x,                             aB1y = pack2(0.0f, 0.0f);

            const ulonglong2* h0b0 = (const ulonglong2*)&sh_h[rs][0][0];
            const ulonglong2* h0b1 = (const ulonglong2*)&sh_h[rs][1][0];
            const ulonglong2* h1b0 = (const ulonglong2*)&sh_h[rs][0][HID];
            const ulonglong2* h1b1 = (const ulonglong2*)&sh_h[rs][1][HID];

            #pragma unroll
            for (int t = 0; t < 16; t++) {        // h0 feeds wA and wI
                ulonglong2 v0 = h0b0[t], v1 = h0b1[t];
                ffma2(aA0x, wA[2*t],   v0.x);
                ffma2(aA1x, wA[2*t],   v1.x);
                ffma2(aB0x, wI[2*t],   v0.x);
                ffma2(aB1x, wI[2*t],   v1.x);
                ffma2(aA0y, wA[2*t+1], v0.y);
                ffma2(aA1y, wA[2*t+1], v1.y);
                ffma2(aB0y, wI[2*t+1], v0.y);
                ffma2(aB1y, wI[2*t+1], v1.y);
            }
            #pragma unroll
            for (int t = 0; t < 16; t++) {        // h1 feeds wH
                ulonglong2 v0 = h1b0[t], v1 = h1b1[t];
                ffma2(aB0x, wH[2*t],   v0.x);
                ffma2(aB1x, wH[2*t],   v1.x);
                ffma2(aB0y, wH[2*t+1], v0.y);
                ffma2(aB1y, wH[2*t+1], v1.y);
            }
            float4 gv = make_float4(hsum2(aA0x, aA0y),
                                    hsum2(aA1x, aA1y),
                                    hsum2(aB0x, aB0y),
                                    hsum2(aB1x, aB1y));
            *(float4*)&sh_s[w][l][0] = gv;        // {gA_b0, gA_b1, gB_b0, gB_b1}
        }
        __syncwarp();
        // ---- warp-local pointwise: lane -> (combo q, unit u) ----
        {
            const bool active = (unsigned)(k - klo) < (unsigned)TLEN;
            float g_i = sh_s[w][j     ][q];   // pre-halved (i row)
            float g_f = sh_s[w][j +  8][q];   // pre-halved (f row)
            float g_c = sh_s[w][j + 16][q];   // full scale (g row)
            float g_o = sh_s[w][j + 24][q];   // pre-halved (o row)
            float iv = fsigmoid_pre(g_i);
            float fv = fsigmoid_pre(g_f);
            float ov = fsigmoid_pre(g_o);
            float cv = tanha(g_c);
            float cn = fmaf(fv, c, iv * cv);
            if (active) {
                c = cn;
                sh_h[ws][bq][hoff] = ov * tanha(c);
            }
        }
        __syncthreads();
    }

    // ---- FC head on final h1 (written at k=4000 -> slot 0) ----
    {
        const int e  = tid & 127;
        const int bb = tid >> 7;
        float acc = b_fc[e];
        const float* wr = W_fc + e * HID;
        const float* hv = &sh_h[0][bb][HID];
        #pragma unroll
        for (int t = 0; t < HID; t += 4) {
            acc = fmaf(wr[t],     hv[t],     acc);
            acc = fmaf(wr[t + 1], hv[t + 1], acc);
            acc = fmaf(wr[t + 2], hv[t + 2], acc);
            acc = fmaf(wr[t + 3], hv[t + 3], acc);
        }
        out[(size_t)(bbase + bb) * 128 + e] = acc;
    }
}

extern "C" void kernel_launch(void* const* d_in, const int* in_sizes, int n_in,
                              void* d_out, int out_size) {
    (void)in_sizes; (void)n_in; (void)out_size;
    lstm2_r16<<<128, NTHR>>>(
        (const float*)d_in[0],   // x
        (const float*)d_in[1],   // W_ih0
        (const float*)d_in[2],   // W_hh0
        (const float*)d_in[3],   // b_ih0
        (const float*)d_in[4],   // b_hh0
        (const float*)d_in[5],   // W_ih1
        (const float*)d_in[6],   // W_hh1
        (const float*)d_in[7],   // b_ih1
        (const float*)d_in[8],   // b_hh1
        (const float*)d_in[9],   // W_fc
        (const float*)d_in[10],  // b_fc
        (float*)d_out);
}

// round 17
// speedup vs baseline: 1.0055x; 1.0055x over previous
#include <cuda_runtime.h>

typedef unsigned long long ull;

#define TLEN 4000
#define HID  64
#define BT   2
#define NTHR 256

__device__ __forceinline__ void ffma2(ull &d, ull a, ull b) {
    asm("fma.rn.f32x2 %0, %1, %2, %0;" : "+l"(d) : "l"(a), "l"(b));
}
__device__ __forceinline__ float2 unpack2(ull v) {
    float2 r;
    asm("mov.b64 {%0, %1}, %2;" : "=f"(r.x), "=f"(r.y) : "l"(v));
    return r;
}
__device__ __forceinline__ ull pack2(float x, float y) {
    ull r;
    asm("mov.b64 %0, {%1, %2};" : "=l"(r) : "f"(x), "f"(y));
    return r;
}
__device__ __forceinline__ float hsum2(ull a, ull b) {
    ull s;
    asm("add.rn.f32x2 %0, %1, %2;" : "=l"(s) : "l"(a), "l"(b));
    float2 f = unpack2(s);
    return f.x + f.y;
}
__device__ __forceinline__ float tanha(float x) {
    float r;
    asm("tanh.approx.f32 %0, %1;" : "=f"(r) : "f"(x));
    return r;
}
__device__ __forceinline__ float fsigmoid(float x) {
    // sigmoid(x) = 0.5*tanh(0.5x) + 0.5  (1 MUFU + FMA)
    return fmaf(tanha(0.5f * x), 0.5f, 0.5f);
}

__global__ void __launch_bounds__(NTHR, 1)
lstm2_r17(const float* __restrict__ x,
          const float* __restrict__ W_ih0,
          const float* __restrict__ W_hh0,
          const float* __restrict__ b_ih0,
          const float* __restrict__ b_hh0,
          const float* __restrict__ W_ih1,
          const float* __restrict__ W_hh1,
          const float* __restrict__ b_ih1,
          const float* __restrict__ b_hh1,
          const float* __restrict__ W_fc,
          const float* __restrict__ b_fc,
          float* __restrict__ out)
{
    __shared__ __align__(16) float sh_x[BT * TLEN];       // 32 KB staged input
    __shared__ __align__(16) float sh_h[2][BT][2 * HID];  // dbl-buffered [h0|h1]
    __shared__ __align__(16) float sh_s[8][32][4];        // warp-local gate xchg

    const int tid   = threadIdx.x;
    const int w     = tid >> 5;
    const int l     = tid & 31;
    const int j     = l & 7;          // unit-local
    const int q     = l >> 3;         // gate index (i,f,g,o) AND pointwise combo
    const int u     = 8 * w + j;      // unit 0..63
    const int row   = q * HID + u;    // gate row this thread owns
    const int bbase = blockIdx.x * BT;

    // Stage x (two contiguous batch rows)
    {
        const float4* xg = (const float4*)(x + (size_t)bbase * TLEN);
        float4* xs = (float4*)sh_x;
        for (int i = tid; i < BT * TLEN / 4; i += NTHR) xs[i] = xg[i];
    }
    ((float2*)sh_h)[tid] = make_float2(0.0f, 0.0f);   // zero both slots (512 f)

    // Per-thread weight rows in registers (packed f32 pairs).
    ull wA[32], wI[32], wH[32];   // W_hh0 / W_ih1 / W_hh1 row `row`
    {
        const ulonglong2* p = (const ulonglong2*)(W_hh0 + row * HID);
        #pragma unroll
        for (int t = 0; t < 16; t++) { ulonglong2 v = p[t]; wA[2*t] = v.x; wA[2*t+1] = v.y; }
        p = (const ulonglong2*)(W_ih1 + row * HID);
        #pragma unroll
        for (int t = 0; t < 16; t++) { ulonglong2 v = p[t]; wI[2*t] = v.x; wI[2*t+1] = v.y; }
        p = (const ulonglong2*)(W_hh1 + row * HID);
        #pragma unroll
        for (int t = 0; t < 16; t++) { ulonglong2 v = p[t]; wH[2*t] = v.x; wH[2*t+1] = v.y; }
    }
    const float wx    = W_ih0[row];
    const float biasA = b_ih0[row] + b_hh0[row];
    const float biasB = b_ih1[row] + b_hh1[row];

    // Pointwise combo for this lane: q -> (layer Lq, batch bq), unit u.
    const int Lq = q >> 1;
    const int bq = q & 1;
    const int hoff = Lq * HID + u;
    // Activity guard: only the lower bound is load-bearing (protects h1 slot 0
    // before its first real write). The q<2 over-store at k=TLEN writes
    // h0(TLEN) into sh_h[0][bq][u], which is never read again — harmless.
    const int klo = (q >= 2) ? 1 : 0;
    float c = 0.0f;

    __syncthreads();

    // Iter k: matvec gA(k) [layer0 step k] + gB(k-1) [layer1 step k-1],
    // warp-local pointwise -> h0(k), h1(k-1). ONE CTA barrier per step.
    for (int k = 0; k <= TLEN; ++k) {
        const int rs = (k + 1) & 1;   // read slot  (= writes of iter k-1)
        const int ws = k & 1;         // write slot
        // ---- fused matvec ----
        {
            const int xk = (k < TLEN) ? k : TLEN - 1;
            const float xa = sh_x[xk];
            const float xb = sh_x[TLEN + xk];
            ull aA0x = pack2(fmaf(xa, wx, biasA), 0.0f), aA0y = pack2(0.0f, 0.0f);
            ull aA1x = pack2(fmaf(xb, wx, biasA), 0.0f), aA1y = pack2(0.0f, 0.0f);
            ull aB0x = pack2(biasB, 0.0f),               aB0y = pack2(0.0f, 0.0f);
            ull aB1x = aB0x,                             aB1y = pack2(0.0f, 0.0f);

            const ulonglong2* h0b0 = (const ulonglong2*)&sh_h[rs][0][0];
            const ulonglong2* h0b1 = (const ulonglong2*)&sh_h[rs][1][0];
            const ulonglong2* h1b0 = (const ulonglong2*)&sh_h[rs][0][HID];
            const ulonglong2* h1b1 = (const ulonglong2*)&sh_h[rs][1][HID];

            #pragma unroll
            for (int t = 0; t < 16; t++) {        // h0 feeds wA and wI
                ulonglong2 v0 = h0b0[t], v1 = h0b1[t];
                ffma2(aA0x, wA[2*t],   v0.x);
                ffma2(aA1x, wA[2*t],   v1.x);
                ffma2(aB0x, wI[2*t],   v0.x);
                ffma2(aB1x, wI[2*t],   v1.x);
                ffma2(aA0y, wA[2*t+1], v0.y);
                ffma2(aA1y, wA[2*t+1], v1.y);
                ffma2(aB0y, wI[2*t+1], v0.y);
                ffma2(aB1y, wI[2*t+1], v1.y);
            }
            #pragma unroll
            for (int t = 0; t < 16; t++) {        // h1 feeds wH
                ulonglong2 v0 = h1b0[t], v1 = h1b1[t];
                ffma2(aB0x, wH[2*t],   v0.x);
                ffma2(aB1x, wH[2*t],   v1.x);
                ffma2(aB0y, wH[2*t+1], v0.y);
                ffma2(aB1y, wH[2*t+1], v1.y);
            }
            float4 gv = make_float4(hsum2(aA0x, aA0y),
                                    hsum2(aA1x, aA1y),
                                    hsum2(aB0x, aB0y),
                                    hsum2(aB1x, aB1y));
            *(float4*)&sh_s[w][l][0] = gv;        // {gA_b0, gA_b1, gB_b0, gB_b1}
        }
        __syncwarp();
        // ---- warp-local pointwise: lane -> (combo q, unit u) ----
        {
            const bool active = (k >= klo);
            float g_i = sh_s[w][j     ][q];
            float g_f = sh_s[w][j +  8][q];
            float g_c = sh_s[w][j + 16][q];
            float g_o = sh_s[w][j + 24][q];
            float iv = fsigmoid(g_i), fv = fsigmoid(g_f), ov = fsigmoid(g_o);
            float cv = tanha(g_c);
            float cn = fmaf(fv, c, iv * cv);
            if (active) {
                c = cn;
                sh_h[ws][bq][hoff] = ov * tanha(c);
            }
        }
        __syncthreads();
    }

    // ---- FC head on final h1 (written at k=4000 -> slot 0) ----
    {
        const int e  = tid & 127;
        const int bb = tid >> 7;
        float acc = b_fc[e];
        const float* wr = W_fc + e * HID;
        const float* hv = &sh_h[0][bb][HID];
        #pragma unroll
        for (int t = 0; t < HID; t += 4) {
            acc = fmaf(wr[t],     hv[t],     acc);
            acc = fmaf(wr[t + 1], hv[t + 1], acc);
            acc = fmaf(wr[t + 2], hv[t + 2], acc);
            acc = fmaf(wr[t + 3], hv[t + 3], acc);
        }
        out[(size_t)(bbase + bb) * 128 + e] = acc;
    }
}

extern "C" void kernel_launch(void* const* d_in, const int* in_sizes, int n_in,
                              void* d_out, int out_size) {
    (void)in_sizes; (void)n_in; (void)out_size;
    lstm2_r17<<<128, NTHR>>>(
        (const float*)d_in[0],   // x
        (const float*)d_in[1],   // W_ih0
        (const float*)d_in[2],   // W_hh0
        (const float*)d_in[3],   // b_ih0
        (const float*)d_in[4],   // b_hh0
        (const float*)d_in[5],   // W_ih1
        (const float*)d_in[6],   // W_hh1
        (const float*)d_in[7],   // b_ih1
        (const float*)d_in[8],   // b_hh1
        (const float*)d_in[9],   // W_fc
        (const float*)d_in[10],  // b_fc
        (float*)d_out);
}